// round 1
// baseline (speedup 1.0000x reference)
#include <cuda_runtime.h>
#include <cuda_bf16.h>

// Mamba block dims (fixed for this problem)
#define BATCH   4
#define LSEQ    2048
#define DMODEL  256
#define DINNER  512
#define DSTATE  16
#define DTRANK  16
#define DCONV   4
#define NROWS   (BATCH * LSEQ)            // 8192
#define XDBL_C  (DTRANK + 2 * DSTATE)     // 48

// ---------------------------------------------------------------------------
// Scratch (static __device__ arrays; no allocations allowed)
// ---------------------------------------------------------------------------
__device__ float g_xz   [NROWS * 2 * DINNER];  // [8192,1024]  (u0 | z)
__device__ float g_u    [NROWS * DINNER];      // post conv+SiLU
__device__ float g_xdbl [NROWS * XDBL_C];      // [8192,48] (dt | B | C)
__device__ float g_delta[NROWS * DINNER];      // softplus(dt @ W_dt^T + b)
__device__ float g_yg   [NROWS * DINNER];      // (y + u*D) * silu(z)

// ---------------------------------------------------------------------------
// Generic NT SGEMM: C[M,N] = A[M,K] * B[N,K]^T   (both row-major, K contiguous)
// 128x128 tile, BK=8, 8x8 per thread, 256 threads.
// Requires: M%128==0, N%128==0, K%8==0, 16B-aligned rows.
// ---------------------------------------------------------------------------
__global__ void __launch_bounds__(256) sgemm128(const float* __restrict__ A,
                                                const float* __restrict__ B,
                                                float* __restrict__ C,
                                                int M, int N, int K)
{
    __shared__ float As[8][128];
    __shared__ float Bs[8][128];

    const int tid = threadIdx.x;
    const int m0 = blockIdx.y * 128;
    const int n0 = blockIdx.x * 128;
    const int tx = tid & 15;        // 0..15 -> 8 cols each
    const int ty = tid >> 4;        // 0..15 -> 8 rows each

    const int lrow = tid >> 1;          // 0..127
    const int lkq  = (tid & 1) * 4;     // 0 or 4

    const float* Aptr = A + (size_t)(m0 + lrow) * K + lkq;
    const float* Bptr = B + (size_t)(n0 + lrow) * K + lkq;

    float acc[8][8];
#pragma unroll
    for (int i = 0; i < 8; i++)
#pragma unroll
        for (int j = 0; j < 8; j++) acc[i][j] = 0.f;

    for (int k0 = 0; k0 < K; k0 += 8) {
        float4 av = *(const float4*)(Aptr + k0);
        float4 bv = *(const float4*)(Bptr + k0);
        As[lkq + 0][lrow] = av.x;
        As[lkq + 1][lrow] = av.y;
        As[lkq + 2][lrow] = av.z;
        As[lkq + 3][lrow] = av.w;
        Bs[lkq + 0][lrow] = bv.x;
        Bs[lkq + 1][lrow] = bv.y;
        Bs[lkq + 2][lrow] = bv.z;
        Bs[lkq + 3][lrow] = bv.w;
        __syncthreads();

#pragma unroll
        for (int kk = 0; kk < 8; kk++) {
            float ra[8], rb[8];
#pragma unroll
            for (int i = 0; i < 8; i++) ra[i] = As[kk][ty * 8 + i];
#pragma unroll
            for (int j = 0; j < 8; j++) rb[j] = Bs[kk][tx * 8 + j];
#pragma unroll
            for (int i = 0; i < 8; i++)
#pragma unroll
                for (int j = 0; j < 8; j++)
                    acc[i][j] = fmaf(ra[i], rb[j], acc[i][j]);
        }
        __syncthreads();
    }

#pragma unroll
    for (int i = 0; i < 8; i++) {
        float* crow = C + (size_t)(m0 + ty * 8 + i) * N + n0 + tx * 8;
#pragma unroll
        for (int j4 = 0; j4 < 2; j4++) {
            float4 v;
            v.x = acc[i][j4 * 4 + 0];
            v.y = acc[i][j4 * 4 + 1];
            v.z = acc[i][j4 * 4 + 2];
            v.w = acc[i][j4 * 4 + 3];
            *(float4*)(crow + j4 * 4) = v;
        }
    }
}

// ---------------------------------------------------------------------------
// Small-N NT SGEMM: 64x64 tile, BK=16, 4x4 per thread, 256 threads.
// Guards N (used for N=48). Requires M%64==0, K%16==0.
// ---------------------------------------------------------------------------
__global__ void __launch_bounds__(256) sgemm64(const float* __restrict__ A,
                                               const float* __restrict__ B,
                                               float* __restrict__ C,
                                               int M, int N, int K)
{
    __shared__ float As[16][64];
    __shared__ float Bs[16][64];

    const int tid = threadIdx.x;
    const int m0 = blockIdx.y * 64;
    const int n0 = blockIdx.x * 64;
    const int tx = tid & 15;
    const int ty = tid >> 4;

    const int lrow = tid >> 2;          // 0..63
    const int lkq  = (tid & 3) * 4;     // 0,4,8,12

    float acc[4][4];
#pragma unroll
    for (int i = 0; i < 4; i++)
#pragma unroll
        for (int j = 0; j < 4; j++) acc[i][j] = 0.f;

    for (int k0 = 0; k0 < K; k0 += 16) {
        float4 av = *(const float4*)(A + (size_t)(m0 + lrow) * K + k0 + lkq);
        float4 bv = make_float4(0.f, 0.f, 0.f, 0.f);
        if (n0 + lrow < N)
            bv = *(const float4*)(B + (size_t)(n0 + lrow) * K + k0 + lkq);
        As[lkq + 0][lrow] = av.x;
        As[lkq + 1][lrow] = av.y;
        As[lkq + 2][lrow] = av.z;
        As[lkq + 3][lrow] = av.w;
        Bs[lkq + 0][lrow] = bv.x;
        Bs[lkq + 1][lrow] = bv.y;
        Bs[lkq + 2][lrow] = bv.z;
        Bs[lkq + 3][lrow] = bv.w;
        __syncthreads();

#pragma unroll
        for (int kk = 0; kk < 16; kk++) {
            float ra[4], rb[4];
#pragma unroll
            for (int i = 0; i < 4; i++) ra[i] = As[kk][ty * 4 + i];
#pragma unroll
            for (int j = 0; j < 4; j++) rb[j] = Bs[kk][tx * 4 + j];
#pragma unroll
            for (int i = 0; i < 4; i++)
#pragma unroll
                for (int j = 0; j < 4; j++)
                    acc[i][j] = fmaf(ra[i], rb[j], acc[i][j]);
        }
        __syncthreads();
    }

#pragma unroll
    for (int i = 0; i < 4; i++)
#pragma unroll
        for (int j = 0; j < 4; j++) {
            int col = n0 + tx * 4 + j;
            if (col < N)
                C[(size_t)(m0 + ty * 4 + i) * N + col] = acc[i][j];
        }
}

// ---------------------------------------------------------------------------
// Depthwise causal conv1d (taps=4) + bias + SiLU.
// u0 lives in g_xz columns [0,512). One thread per (row, d).
// ---------------------------------------------------------------------------
__global__ void __launch_bounds__(256) conv_silu_k(const float* __restrict__ xz,
                                                   const float* __restrict__ w,
                                                   const float* __restrict__ bias,
                                                   float* __restrict__ u)
{
    int idx = blockIdx.x * 256 + threadIdx.x;       // 0 .. NROWS*DINNER-1
    int r = idx >> 9;           // row = b*L + t
    int d = idx & 511;
    int b = r >> 11;
    int t = r & 2047;

    const float* wd = w + d * 4;
    float acc = bias[d];
#pragma unroll
    for (int k = 0; k < 4; k++) {
        int tt = t - 3 + k;
        if (tt >= 0)
            acc = fmaf(xz[(size_t)(b * LSEQ + tt) * (2 * DINNER) + d], wd[k], acc);
    }
    // SiLU
    u[idx] = acc / (1.f + __expf(-acc));
}

// ---------------------------------------------------------------------------
// delta = softplus(xdbl[:, :16] @ W_dt^T + b_dt)   one thread per (row, d)
// ---------------------------------------------------------------------------
__global__ void __launch_bounds__(256) delta_k(const float* __restrict__ xdbl,
                                               const float* __restrict__ W_dt,
                                               const float* __restrict__ b_dt,
                                               float* __restrict__ delta)
{
    int idx = blockIdx.x * 256 + threadIdx.x;
    int r = idx >> 9;
    int d = idx & 511;

    const float4* xr = (const float4*)(xdbl + (size_t)r * XDBL_C);
    const float4* wd = (const float4*)(W_dt + d * DTRANK);
    float acc = b_dt[d];
#pragma unroll
    for (int q = 0; q < 4; q++) {
        float4 xv = xr[q];
        float4 wv = wd[q];
        acc = fmaf(xv.x, wv.x, acc);
        acc = fmaf(xv.y, wv.y, acc);
        acc = fmaf(xv.z, wv.z, acc);
        acc = fmaf(xv.w, wv.w, acc);
    }
    // softplus, overflow-safe
    delta[idx] = (acc > 20.f) ? acc : log1pf(expf(acc));
}

// ---------------------------------------------------------------------------
// Selective scan, fused with skip (+u*D) and gate (*silu(z)).
// Block = (batch b, 16 channels).  256 threads = 16 d-lanes x 16 states.
// Each thread owns one state h[d,n]; per-step output is a 16-lane shfl reduce.
// Time is staged through shared memory in chunks of 64 steps.
// ---------------------------------------------------------------------------
#define SCAN_TT 64

__global__ void __launch_bounds__(256) scan_k(const float* __restrict__ delta,
                                              const float* __restrict__ u,
                                              const float* __restrict__ xdbl,
                                              const float* __restrict__ A_log,
                                              const float* __restrict__ Dskip,
                                              const float* __restrict__ xz,
                                              float* __restrict__ yg)
{
    __shared__ float sD[SCAN_TT][16];
    __shared__ float sU[SCAN_TT][16];
    __shared__ float sB[SCAN_TT][16];
    __shared__ float sC[SCAN_TT][16];
    __shared__ float sZ[SCAN_TT][16];

    const int tid = threadIdx.x;
    const int b  = blockIdx.x >> 5;            // 0..3
    const int d0 = (blockIdx.x & 31) << 4;     // 0,16,...,496
    const int dl = tid >> 4;                   // 0..15 local channel
    const int n  = tid & 15;                   // state index
    const int d  = d0 + dl;

    const float a_dn = -expf(A_log[d * DSTATE + n]);   // A[d,n] (negative)
    const float Dk   = Dskip[d];
    float h = 0.f;

    for (int t0 = 0; t0 < LSEQ; t0 += SCAN_TT) {
        // cooperative staging of this time chunk
        for (int i = tid; i < SCAN_TT * 16; i += 256) {
            int tt = i >> 4;
            int c  = i & 15;
            int r  = b * LSEQ + t0 + tt;
            sD[tt][c] = delta[(size_t)r * DINNER + d0 + c];
            sU[tt][c] = u    [(size_t)r * DINNER + d0 + c];
            sB[tt][c] = xdbl [(size_t)r * XDBL_C + DTRANK + c];
            sC[tt][c] = xdbl [(size_t)r * XDBL_C + DTRANK + DSTATE + c];
            sZ[tt][c] = xz   [(size_t)r * (2 * DINNER) + DINNER + d0 + c];
        }
        __syncthreads();

#pragma unroll 4
        for (int tt = 0; tt < SCAN_TT; tt++) {
            float dv = sD[tt][dl];                 // broadcast across 16 n-lanes
            float uv = sU[tt][dl];
            float dA = __expf(dv * a_dn);          // in (0,1]
            h = fmaf(dA, h, dv * uv * sB[tt][n]);
            float p = h * sC[tt][n];
            // reduce over the aligned 16-lane state group
            p += __shfl_xor_sync(0xffffffffu, p, 8);
            p += __shfl_xor_sync(0xffffffffu, p, 4);
            p += __shfl_xor_sync(0xffffffffu, p, 2);
            p += __shfl_xor_sync(0xffffffffu, p, 1);
            if (n == 0) {
                float zv = sZ[tt][dl];
                float gate = zv / (1.f + __expf(-zv));   // silu(z)
                int r = b * LSEQ + t0 + tt;
                yg[(size_t)r * DINNER + d] = (p + uv * Dk) * gate;
            }
        }
        __syncthreads();
    }
}

// ---------------------------------------------------------------------------
// Launch
// ---------------------------------------------------------------------------
extern "C" void kernel_launch(void* const* d_in, const int* in_sizes, int n_in,
                              void* d_out, int out_size)
{
    const float* x      = (const float*)d_in[0];   // [4,2048,256]
    const float* W_in   = (const float*)d_in[1];   // [1024,256]
    const float* conv_w = (const float*)d_in[2];   // [512,1,4]
    const float* conv_b = (const float*)d_in[3];   // [512]
    const float* W_xp   = (const float*)d_in[4];   // [48,512]
    const float* W_dt   = (const float*)d_in[5];   // [512,16]
    const float* b_dt   = (const float*)d_in[6];   // [512]
    const float* A_log  = (const float*)d_in[7];   // [512,16]
    const float* Dsk    = (const float*)d_in[8];   // [512]
    const float* W_out  = (const float*)d_in[9];   // [256,512]
    float* out = (float*)d_out;                    // [4,2048,256]

    float *p_xz, *p_u, *p_xdbl, *p_delta, *p_yg;
    cudaGetSymbolAddress((void**)&p_xz,    g_xz);
    cudaGetSymbolAddress((void**)&p_u,     g_u);
    cudaGetSymbolAddress((void**)&p_xdbl,  g_xdbl);
    cudaGetSymbolAddress((void**)&p_delta, g_delta);
    cudaGetSymbolAddress((void**)&p_yg,    g_yg);

    // 1. xz = x @ W_in^T   [8192,1024]
    sgemm128<<<dim3((2 * DINNER) / 128, NROWS / 128), 256>>>(
        x, W_in, p_xz, NROWS, 2 * DINNER, DMODEL);

    // 2. depthwise causal conv + SiLU -> u
    conv_silu_k<<<(NROWS * DINNER) / 256, 256>>>(p_xz, conv_w, conv_b, p_u);

    // 3. xdbl = u @ W_xproj^T   [8192,48]
    sgemm64<<<dim3(1, NROWS / 64), 256>>>(p_u, W_xp, p_xdbl, NROWS, XDBL_C, DINNER);

    // 4. delta = softplus(dt @ W_dt^T + b_dt)   [8192,512]
    delta_k<<<(NROWS * DINNER) / 256, 256>>>(p_xdbl, W_dt, b_dt, p_delta);

    // 5. selective scan + skip + gate -> yg   [8192,512]
    scan_k<<<BATCH * (DINNER / 16), 256>>>(p_delta, p_u, p_xdbl, A_log, Dsk, p_xz, p_yg);

    // 6. out = yg @ W_out^T   [8192,256]
    sgemm128<<<dim3(DMODEL / 128, NROWS / 128), 256>>>(
        p_yg, W_out, out, NROWS, DMODEL, DINNER);
}

// round 17
// speedup vs baseline: 1.1427x; 1.1427x over previous
#include <cuda_runtime.h>
#include <cuda_bf16.h>

// Mamba block dims (fixed for this problem)
#define BATCH   4
#define LSEQ    2048
#define DMODEL  256
#define DINNER  512
#define DSTATE  16
#define DTRANK  16
#define DCONV   4
#define NROWS   (BATCH * LSEQ)            // 8192
#define XDBL_C  (DTRANK + 2 * DSTATE)     // 48

// ---------------------------------------------------------------------------
// Scratch (static __device__ arrays; no allocations allowed)
// ---------------------------------------------------------------------------
__device__ float g_xz   [NROWS * 2 * DINNER];  // [8192,1024]  (u0 | z)
__device__ float g_u    [NROWS * DINNER];      // post conv+SiLU
__device__ float g_xdbl [NROWS * XDBL_C];      // [8192,48] (dt | B | C)
__device__ float g_yg   [NROWS * DINNER];      // (y + u*D) * silu(z)

// ---------------------------------------------------------------------------
// Double-buffered NT SGEMM: C[M,N] = A[M,K] * B[N,K]^T  (row-major, K contig)
// 128x128 tile, BK=8, 8x8 per thread, 256 threads, smem ping-pong,
// float4 shared-memory fragment loads, one __syncthreads per k-tile.
// Requires: M%128==0, N%128==0, K%8==0.
// ---------------------------------------------------------------------------
__global__ void __launch_bounds__(256) sgemm128(const float* __restrict__ A,
                                                const float* __restrict__ B,
                                                float* __restrict__ C,
                                                int M, int N, int K)
{
    __shared__ float As[2][8][128];
    __shared__ float Bs[2][8][128];

    const int tid = threadIdx.x;
    const int m0 = blockIdx.y * 128;
    const int n0 = blockIdx.x * 128;
    const int tx = tid & 15;        // 0..15 -> 8 cols each
    const int ty = tid >> 4;        // 0..15 -> 8 rows each

    const int lrow = tid >> 1;          // 0..127
    const int lkq  = (tid & 1) * 4;     // 0 or 4

    const float* Aptr = A + (size_t)(m0 + lrow) * K + lkq;
    const float* Bptr = B + (size_t)(n0 + lrow) * K + lkq;

    float acc[8][8];
#pragma unroll
    for (int i = 0; i < 8; i++)
#pragma unroll
        for (int j = 0; j < 8; j++) acc[i][j] = 0.f;

    // prime buffer 0
    {
        float4 av = *(const float4*)(Aptr);
        float4 bv = *(const float4*)(Bptr);
        As[0][lkq + 0][lrow] = av.x;
        As[0][lkq + 1][lrow] = av.y;
        As[0][lkq + 2][lrow] = av.z;
        As[0][lkq + 3][lrow] = av.w;
        Bs[0][lkq + 0][lrow] = bv.x;
        Bs[0][lkq + 1][lrow] = bv.y;
        Bs[0][lkq + 2][lrow] = bv.z;
        Bs[0][lkq + 3][lrow] = bv.w;
    }
    __syncthreads();

    int buf = 0;
    for (int k0 = 8; k0 < K; k0 += 8) {
        // prefetch next tile to registers (overlaps with compute below)
        float4 av = *(const float4*)(Aptr + k0);
        float4 bv = *(const float4*)(Bptr + k0);

#pragma unroll
        for (int kk = 0; kk < 8; kk++) {
            float4 a0 = *(const float4*)&As[buf][kk][ty * 8];
            float4 a1 = *(const float4*)&As[buf][kk][ty * 8 + 4];
            float4 b0 = *(const float4*)&Bs[buf][kk][tx * 8];
            float4 b1 = *(const float4*)&Bs[buf][kk][tx * 8 + 4];
            const float ra[8] = {a0.x, a0.y, a0.z, a0.w, a1.x, a1.y, a1.z, a1.w};
            const float rb[8] = {b0.x, b0.y, b0.z, b0.w, b1.x, b1.y, b1.z, b1.w};
#pragma unroll
            for (int i = 0; i < 8; i++)
#pragma unroll
                for (int j = 0; j < 8; j++)
                    acc[i][j] = fmaf(ra[i], rb[j], acc[i][j]);
        }

        // write prefetched tile into the other buffer (no reader conflict)
        int nb = buf ^ 1;
        As[nb][lkq + 0][lrow] = av.x;
        As[nb][lkq + 1][lrow] = av.y;
        As[nb][lkq + 2][lrow] = av.z;
        As[nb][lkq + 3][lrow] = av.w;
        Bs[nb][lkq + 0][lrow] = bv.x;
        Bs[nb][lkq + 1][lrow] = bv.y;
        Bs[nb][lkq + 2][lrow] = bv.z;
        Bs[nb][lkq + 3][lrow] = bv.w;
        __syncthreads();
        buf = nb;
    }

    // last tile
#pragma unroll
    for (int kk = 0; kk < 8; kk++) {
        float4 a0 = *(const float4*)&As[buf][kk][ty * 8];
        float4 a1 = *(const float4*)&As[buf][kk][ty * 8 + 4];
        float4 b0 = *(const float4*)&Bs[buf][kk][tx * 8];
        float4 b1 = *(const float4*)&Bs[buf][kk][tx * 8 + 4];
        const float ra[8] = {a0.x, a0.y, a0.z, a0.w, a1.x, a1.y, a1.z, a1.w};
        const float rb[8] = {b0.x, b0.y, b0.z, b0.w, b1.x, b1.y, b1.z, b1.w};
#pragma unroll
        for (int i = 0; i < 8; i++)
#pragma unroll
            for (int j = 0; j < 8; j++)
                acc[i][j] = fmaf(ra[i], rb[j], acc[i][j]);
    }

#pragma unroll
    for (int i = 0; i < 8; i++) {
        float* crow = C + (size_t)(m0 + ty * 8 + i) * N + n0 + tx * 8;
#pragma unroll
        for (int j4 = 0; j4 < 2; j4++) {
            float4 v;
            v.x = acc[i][j4 * 4 + 0];
            v.y = acc[i][j4 * 4 + 1];
            v.z = acc[i][j4 * 4 + 2];
            v.w = acc[i][j4 * 4 + 3];
            *(float4*)(crow + j4 * 4) = v;
        }
    }
}

// ---------------------------------------------------------------------------
// Small-N NT SGEMM: 64x64 tile, BK=16, 4x4 per thread, 256 threads.
// Guards N (used for N=48). Requires M%64==0, K%16==0.
// ---------------------------------------------------------------------------
__global__ void __launch_bounds__(256) sgemm64(const float* __restrict__ A,
                                               const float* __restrict__ B,
                                               float* __restrict__ C,
                                               int M, int N, int K)
{
    __shared__ float As[16][64];
    __shared__ float Bs[16][64];

    const int tid = threadIdx.x;
    const int m0 = blockIdx.y * 64;
    const int n0 = blockIdx.x * 64;
    const int tx = tid & 15;
    const int ty = tid >> 4;

    const int lrow = tid >> 2;          // 0..63
    const int lkq  = (tid & 3) * 4;     // 0,4,8,12

    float acc[4][4];
#pragma unroll
    for (int i = 0; i < 4; i++)
#pragma unroll
        for (int j = 0; j < 4; j++) acc[i][j] = 0.f;

    for (int k0 = 0; k0 < K; k0 += 16) {
        float4 av = *(const float4*)(A + (size_t)(m0 + lrow) * K + k0 + lkq);
        float4 bv = make_float4(0.f, 0.f, 0.f, 0.f);
        if (n0 + lrow < N)
            bv = *(const float4*)(B + (size_t)(n0 + lrow) * K + k0 + lkq);
        As[lkq + 0][lrow] = av.x;
        As[lkq + 1][lrow] = av.y;
        As[lkq + 2][lrow] = av.z;
        As[lkq + 3][lrow] = av.w;
        Bs[lkq + 0][lrow] = bv.x;
        Bs[lkq + 1][lrow] = bv.y;
        Bs[lkq + 2][lrow] = bv.z;
        Bs[lkq + 3][lrow] = bv.w;
        __syncthreads();

#pragma unroll
        for (int kk = 0; kk < 16; kk++) {
            float ra[4], rb[4];
#pragma unroll
            for (int i = 0; i < 4; i++) ra[i] = As[kk][ty * 4 + i];
#pragma unroll
            for (int j = 0; j < 4; j++) rb[j] = Bs[kk][tx * 4 + j];
#pragma unroll
            for (int i = 0; i < 4; i++)
#pragma unroll
                for (int j = 0; j < 4; j++)
                    acc[i][j] = fmaf(ra[i], rb[j], acc[i][j]);
        }
        __syncthreads();
    }

#pragma unroll
    for (int i = 0; i < 4; i++)
#pragma unroll
        for (int j = 0; j < 4; j++) {
            int col = n0 + tx * 4 + j;
            if (col < N)
                C[(size_t)(m0 + ty * 4 + i) * N + col] = acc[i][j];
        }
}

// ---------------------------------------------------------------------------
// Depthwise causal conv1d (taps=4) + bias + SiLU, float4 over channels.
// u0 lives in g_xz columns [0,512). One thread per (row, 4 channels).
// ---------------------------------------------------------------------------
__global__ void __launch_bounds__(256) conv_silu_k(const float* __restrict__ xz,
                                                   const float* __restrict__ w,
                                                   const float* __restrict__ bias,
                                                   float* __restrict__ u)
{
    int idx = blockIdx.x * 256 + threadIdx.x;       // over NROWS * DINNER/4
    int r  = idx >> 7;           // row = b*L + t
    int dg = (idx & 127) << 2;   // channel group base
    int b = r >> 11;
    int t = r & 2047;

    float4 w0 = *(const float4*)(w + (dg + 0) * 4);   // taps of channel dg+0
    float4 w1 = *(const float4*)(w + (dg + 1) * 4);
    float4 w2 = *(const float4*)(w + (dg + 2) * 4);
    float4 w3 = *(const float4*)(w + (dg + 3) * 4);
    float4 acc = *(const float4*)(bias + dg);

#pragma unroll
    for (int k = 0; k < 4; k++) {
        int tt = t - 3 + k;
        if (tt >= 0) {
            float4 xv = *(const float4*)(xz + (size_t)(b * LSEQ + tt) * (2 * DINNER) + dg);
            acc.x = fmaf(xv.x, ((const float*)&w0)[k], acc.x);
            acc.y = fmaf(xv.y, ((const float*)&w1)[k], acc.y);
            acc.z = fmaf(xv.z, ((const float*)&w2)[k], acc.z);
            acc.w = fmaf(xv.w, ((const float*)&w3)[k], acc.w);
        }
    }
    // SiLU
    acc.x = acc.x / (1.f + __expf(-acc.x));
    acc.y = acc.y / (1.f + __expf(-acc.y));
    acc.z = acc.z / (1.f + __expf(-acc.z));
    acc.w = acc.w / (1.f + __expf(-acc.w));
    *(float4*)(u + (size_t)r * DINNER + dg) = acc;
}

// ---------------------------------------------------------------------------
// Selective scan, fused with:
//   - delta = softplus(dt @ W_dt^T + b_dt)  (computed from staged xdbl chunk)
//   - skip (+u*D) and gate (*silu(z))
// Block = (batch b, 16 channels).  256 threads = 16 d-lanes x 16 states.
// Each thread owns one state h[d,n]; per-step output is a 16-lane shfl reduce.
// Time is staged through shared memory in chunks of 64 steps.
// ---------------------------------------------------------------------------
#define SCAN_TT 64

__global__ void __launch_bounds__(256) scan_k(const float* __restrict__ u,
                                              const float* __restrict__ xdbl,
                                              const float* __restrict__ W_dt,
                                              const float* __restrict__ b_dt,
                                              const float* __restrict__ A_log,
                                              const float* __restrict__ Dskip,
                                              const float* __restrict__ xz,
                                              float* __restrict__ yg)
{
    __shared__ float sX[SCAN_TT][XDBL_C];   // dt | B | C  (48 floats per row)
    __shared__ float sD[SCAN_TT][16];       // delta for local channels
    __shared__ float sU[SCAN_TT][16];
    __shared__ float sZ[SCAN_TT][16];

    const int tid = threadIdx.x;
    const int b  = blockIdx.x >> 5;            // 0..3
    const int d0 = (blockIdx.x & 31) << 4;     // 0,16,...,496
    const int dl = tid >> 4;                   // 0..15 local channel
    const int n  = tid & 15;                   // state index
    const int d  = d0 + dl;

    const float a_dn = -expf(A_log[d * DSTATE + n]);   // A[d,n] (negative)
    const float Dk   = Dskip[d];

    // this thread also computes delta for local channel cc = tid & 15
    const int cc = tid & 15;
    float wv[DTRANK];
#pragma unroll
    for (int q = 0; q < DTRANK; q++) wv[q] = W_dt[(d0 + cc) * DTRANK + q];
    const float bb = b_dt[d0 + cc];

    float h = 0.f;

    for (int t0 = 0; t0 < LSEQ; t0 += SCAN_TT) {
        // ---- stage xdbl chunk (64 x 48 floats = 768 float4) ----
        {
            const float4* src = (const float4*)(xdbl + (size_t)(b * LSEQ + t0) * XDBL_C);
            float4* dst = (float4*)&sX[0][0];
#pragma unroll
            for (int i = 0; i < 3; i++) dst[tid + i * 256] = src[tid + i * 256];
        }
        // ---- stage u and z (64 x 16 floats each = 256 float4 each) ----
        {
            int tt = tid >> 2;
            int q4 = (tid & 3) * 4;
            size_t r = (size_t)(b * LSEQ + t0 + tt);
            *(float4*)&sU[tt][q4] = *(const float4*)(u  + r * DINNER + d0 + q4);
            *(float4*)&sZ[tt][q4] = *(const float4*)(xz + r * (2 * DINNER) + DINNER + d0 + q4);
        }
        __syncthreads();

        // ---- compute delta for this chunk from staged dt rows ----
#pragma unroll
        for (int p = 0; p < 4; p++) {
            int tt = (tid >> 4) + p * 16;
            float acc = bb;
#pragma unroll
            for (int q = 0; q < DTRANK; q++)
                acc = fmaf(sX[tt][q], wv[q], acc);
            sD[tt][cc] = (acc > 20.f) ? acc : log1pf(expf(acc));
        }
        __syncthreads();

        // ---- serial scan over the chunk ----
#pragma unroll 4
        for (int tt = 0; tt < SCAN_TT; tt++) {
            float dv = sD[tt][dl];                 // broadcast across 16 n-lanes
            float uv = sU[tt][dl];
            float dA = __expf(dv * a_dn);          // in (0,1]
            h = fmaf(dA, h, dv * uv * sX[tt][DTRANK + n]);
            float p = h * sX[tt][DTRANK + DSTATE + n];
            // reduce over the aligned 16-lane state group
            p += __shfl_xor_sync(0xffffffffu, p, 8);
            p += __shfl_xor_sync(0xffffffffu, p, 4);
            p += __shfl_xor_sync(0xffffffffu, p, 2);
            p += __shfl_xor_sync(0xffffffffu, p, 1);
            if (n == 0) {
                float zv = sZ[tt][dl];
                float gate = zv / (1.f + __expf(-zv));   // silu(z)
                int r = b * LSEQ + t0 + tt;
                yg[(size_t)r * DINNER + d] = (p + uv * Dk) * gate;
            }
        }
        __syncthreads();
    }
}

// ---------------------------------------------------------------------------
// Launch
// ---------------------------------------------------------------------------
extern "C" void kernel_launch(void* const* d_in, const int* in_sizes, int n_in,
                              void* d_out, int out_size)
{
    const float* x      = (const float*)d_in[0];   // [4,2048,256]
    const float* W_in   = (const float*)d_in[1];   // [1024,256]
    const float* conv_w = (const float*)d_in[2];   // [512,1,4]
    const float* conv_b = (const float*)d_in[3];   // [512]
    const float* W_xp   = (const float*)d_in[4];   // [48,512]
    const float* W_dt   = (const float*)d_in[5];   // [512,16]
    const float* b_dt   = (const float*)d_in[6];   // [512]
    const float* A_log  = (const float*)d_in[7];   // [512,16]
    const float* Dsk    = (const float*)d_in[8];   // [512]
    const float* W_out  = (const float*)d_in[9];   // [256,512]
    float* out = (float*)d_out;                    // [4,2048,256]

    float *p_xz, *p_u, *p_xdbl, *p_yg;
    cudaGetSymbolAddress((void**)&p_xz,    g_xz);
    cudaGetSymbolAddress((void**)&p_u,     g_u);
    cudaGetSymbolAddress((void**)&p_xdbl,  g_xdbl);
    cudaGetSymbolAddress((void**)&p_yg,    g_yg);

    // 1. xz = x @ W_in^T   [8192,1024]
    sgemm128<<<dim3((2 * DINNER) / 128, NROWS / 128), 256>>>(
        x, W_in, p_xz, NROWS, 2 * DINNER, DMODEL);

    // 2. depthwise causal conv + SiLU -> u
    conv_silu_k<<<(NROWS * DINNER / 4) / 256, 256>>>(p_xz, conv_w, conv_b, p_u);

    // 3. xdbl = u @ W_xproj^T   [8192,48]
    sgemm64<<<dim3(1, NROWS / 64), 256>>>(p_u, W_xp, p_xdbl, NROWS, XDBL_C, DINNER);

    // 4. selective scan (+fused delta, skip, gate) -> yg   [8192,512]
    scan_k<<<BATCH * (DINNER / 16), 256>>>(p_u, p_xdbl, W_dt, b_dt, A_log, Dsk, p_xz, p_yg);

    // 5. out = yg @ W_out^T   [8192,256]
    sgemm128<<<dim3(DMODEL / 128, NROWS / 128), 256>>>(
        p_yg, W_out, out, NROWS, DMODEL, DINNER);
}